// round 1
// baseline (speedup 1.0000x reference)
#include <cuda_runtime.h>
#include <math.h>

#define S_LEN  2048
#define HID    2048
#define NH     16
#define QLORA  1536
#define KVLORA 512
#define NOPE   128
#define ROPED  64
#define VD     128
#define QHD    192          // NOPE + ROPED
#define KVD    256          // NOPE + VD

// ---------------- scratch (no cudaMalloc allowed) ----------------
__device__ float g_qlat[S_LEN * QLORA];           // q latent (rmsnorm in-place)
__device__ float g_ckv [S_LEN * (KVLORA + ROPED)];// kv_a output
__device__ float g_ckvn[S_LEN * KVLORA];          // normalized compressed kv
__device__ float g_q   [S_LEN * NH * QHD];        // q (rope applied in-place)
__device__ float g_kv  [S_LEN * NH * KVD];        // k_nope | v per head
__device__ float g_kpe [S_LEN * ROPED];           // roped k_pe (shared across heads)
__device__ float g_attn[S_LEN * NH * VD];         // attention output

// ---------------- GEMM: C[M,N] = A[M,K] @ B[N,K]^T (all row-major) --------
// tiles 64x64, K-tile 16, 256 threads, per-thread 4x4
#define GTM 64
#define GTN 64
#define GTK 16

__global__ __launch_bounds__(256) void gemm_nt(
    const float* __restrict__ A, const float* __restrict__ B,
    float* __restrict__ C, int M, int N, int K)
{
    __shared__ float As[GTK][GTM + 4];
    __shared__ float Bs[GTK][GTN + 4];

    const int tid = threadIdx.x;
    const int tx  = tid & 15;
    const int ty  = tid >> 4;
    const int bm  = blockIdx.y * GTM;
    const int bn  = blockIdx.x * GTN;

    const int lr = tid >> 2;         // 0..63 row within tile
    const int lk = (tid & 3) * 4;    // 0,4,8,12

    float acc[4][4] = {};

    const float* Ap = A + (size_t)(bm + lr) * K + lk;
    const float* Bp = B + (size_t)(bn + lr) * K + lk;

    for (int k0 = 0; k0 < K; k0 += GTK) {
        float4 a4 = *(const float4*)(Ap + k0);
        float4 b4 = *(const float4*)(Bp + k0);
        __syncthreads();
        As[lk + 0][lr] = a4.x; As[lk + 1][lr] = a4.y;
        As[lk + 2][lr] = a4.z; As[lk + 3][lr] = a4.w;
        Bs[lk + 0][lr] = b4.x; Bs[lk + 1][lr] = b4.y;
        Bs[lk + 2][lr] = b4.z; Bs[lk + 3][lr] = b4.w;
        __syncthreads();
#pragma unroll
        for (int kk = 0; kk < GTK; kk++) {
            float4 av = *(const float4*)&As[kk][ty * 4];
            float4 bv = *(const float4*)&Bs[kk][tx * 4];
            float a[4] = {av.x, av.y, av.z, av.w};
            float b[4] = {bv.x, bv.y, bv.z, bv.w};
#pragma unroll
            for (int i = 0; i < 4; i++)
#pragma unroll
                for (int j = 0; j < 4; j++)
                    acc[i][j] += a[i] * b[j];
        }
    }
#pragma unroll
    for (int i = 0; i < 4; i++) {
        float4 o = make_float4(acc[i][0], acc[i][1], acc[i][2], acc[i][3]);
        *(float4*)&C[(size_t)(bm + ty * 4 + i) * N + bn + tx * 4] = o;
    }
}

// ---------------- RMSNorm over rows ----------------
__global__ __launch_bounds__(256) void rmsnorm_kernel(
    const float* __restrict__ x, const float* __restrict__ w,
    float* __restrict__ y, int ncols, int xstride, int ystride)
{
    const int row = blockIdx.x;
    const float* xr = x + (size_t)row * xstride;
    float* yr = y + (size_t)row * ystride;

    float ss = 0.f;
    for (int c = threadIdx.x; c < ncols; c += 256) {
        float v = xr[c];
        ss += v * v;
    }
    __shared__ float red[8];
#pragma unroll
    for (int o = 16; o; o >>= 1) ss += __shfl_xor_sync(~0u, ss, o);
    if ((threadIdx.x & 31) == 0) red[threadIdx.x >> 5] = ss;
    __syncthreads();
    if (threadIdx.x < 32) {
        float v = (threadIdx.x < 8) ? red[threadIdx.x] : 0.f;
#pragma unroll
        for (int o = 4; o; o >>= 1) v += __shfl_xor_sync(~0u, v, o);
        if (threadIdx.x == 0) red[0] = v;
    }
    __syncthreads();
    const float inv = rsqrtf(red[0] / (float)ncols + 1e-6f);
    for (int c = threadIdx.x; c < ncols; c += 256)
        yr[c] = xr[c] * inv * w[c];
}

// ---------------- RoPE: q_pe in-place, k_pe -> g_kpe ----------------
__global__ __launch_bounds__(544) void rope_kernel(
    float* __restrict__ q, const float* __restrict__ ckv, float* __restrict__ kpe)
{
    const int s = blockIdx.x;
    const int t = threadIdx.x;        // 0..543 = 17 warps
    const int h = t >> 5;
    const int d = t & 31;

    const float f = powf(10000.0f, -(float)d / 32.0f);
    float sn, cs;
    sincosf((float)s * f, &sn, &cs);

    if (h < NH) {
        float* p = q + (size_t)s * (NH * QHD) + h * QHD + NOPE;
        float x1 = p[d], x2 = p[d + 32];
        p[d]      = x1 * cs - x2 * sn;
        p[d + 32] = x2 * cs + x1 * sn;
    } else {
        const float* p = ckv + (size_t)s * (KVLORA + ROPED) + KVLORA;
        float x1 = p[d], x2 = p[d + 32];
        kpe[s * ROPED + d]      = x1 * cs - x2 * sn;
        kpe[s * ROPED + d + 32] = x2 * cs + x1 * sn;
    }
}

// ---------------- Flash attention (causal), fp32 ----------------
// grid (S/BQ, NH), 256 threads = 8 warps; warp w owns q-rows w*4..w*4+3
#define BQ 32
#define BK 64
#define KPAD 196   // 196*4B = 784B row stride -> LDS.128 phase-conflict-free

__global__ __launch_bounds__(256) void attn_kernel(
    const float* __restrict__ q, const float* __restrict__ kv,
    const float* __restrict__ kpe, float* __restrict__ out)
{
    extern __shared__ float sm[];
    float* Qs = sm;                       // [BQ][KPAD]
    float* Ks = Qs + BQ * KPAD;           // [BK][KPAD]
    float* Vs = Ks + BK * KPAD;           // [BK][VD]
    float* Ps = Vs + BK * VD;             // [BQ][BK]

    const int qb   = blockIdx.x;
    const int h    = blockIdx.y;
    const int tid  = threadIdx.x;
    const int w    = tid >> 5;
    const int lane = tid & 31;

    // load Q tile (rope already applied)
    for (int idx = tid; idx < BQ * QHD; idx += 256) {
        int r = idx / QHD, d = idx % QHD;
        Qs[r * KPAD + d] = q[(size_t)(qb * BQ + r) * (NH * QHD) + h * QHD + d];
    }

    float acc[4][4] = {};
    float m_i[4] = {-1e30f, -1e30f, -1e30f, -1e30f};
    float l_i[4] = {};

    const int q_hi = qb * BQ + BQ - 1;
    const int nkb  = q_hi / BK + 1;
    const float scale = 0.07216878364870323f;  // 192^-0.5

    for (int kb = 0; kb < nkb; kb++) {
        __syncthreads();
        // K tile: [d<128 from kv nope | d>=128 from kpe]
        for (int idx = tid; idx < BK * QHD; idx += 256) {
            int r = idx / QHD, d = idx % QHD;
            int kg = kb * BK + r;
            float v = (d < NOPE)
                ? kv[(size_t)kg * (NH * KVD) + h * KVD + d]
                : kpe[kg * ROPED + (d - NOPE)];
            Ks[r * KPAD + d] = v;
        }
        // V tile
        for (int idx = tid; idx < BK * VD; idx += 256) {
            int r = idx >> 7, d = idx & 127;
            Vs[r * VD + d] =
                kv[(size_t)(kb * BK + r) * (NH * KVD) + h * KVD + NOPE + d];
        }
        __syncthreads();

        // scores: rows w*4+i, cols lane*2+{0,1}
        float s0[4][2] = {};
#pragma unroll 2
        for (int d = 0; d < QHD; d += 4) {
            float4 k0 = *(const float4*)&Ks[(lane * 2 + 0) * KPAD + d];
            float4 k1 = *(const float4*)&Ks[(lane * 2 + 1) * KPAD + d];
#pragma unroll
            for (int i = 0; i < 4; i++) {
                float4 qv = *(const float4*)&Qs[(w * 4 + i) * KPAD + d];
                s0[i][0] += qv.x * k0.x + qv.y * k0.y + qv.z * k0.z + qv.w * k0.w;
                s0[i][1] += qv.x * k1.x + qv.y * k1.y + qv.z * k1.z + qv.w * k1.w;
            }
        }

        // online softmax per row (warp-wide; each lane has 2 cols)
#pragma unroll
        for (int i = 0; i < 4; i++) {
            const int qg = qb * BQ + w * 4 + i;
            const int kg0 = kb * BK + lane * 2;
            float v0 = (kg0     <= qg) ? s0[i][0] * scale : -1e30f;
            float v1 = (kg0 + 1 <= qg) ? s0[i][1] * scale : -1e30f;
            float mloc = fmaxf(v0, v1);
#pragma unroll
            for (int o = 16; o; o >>= 1)
                mloc = fmaxf(mloc, __shfl_xor_sync(~0u, mloc, o));
            const float mnew = fmaxf(m_i[i], mloc);
            const float corr = __expf(m_i[i] - mnew);
            m_i[i] = mnew;
            const float p0 = __expf(v0 - mnew);
            const float p1 = __expf(v1 - mnew);
            float rs = p0 + p1;
#pragma unroll
            for (int o = 16; o; o >>= 1) rs += __shfl_xor_sync(~0u, rs, o);
            l_i[i] = l_i[i] * corr + rs;
#pragma unroll
            for (int j = 0; j < 4; j++) acc[i][j] *= corr;
            *(float2*)&Ps[(w * 4 + i) * BK + lane * 2] = make_float2(p0, p1);
        }
        __syncwarp();

        // PV: cols lane*4..lane*4+3 of V (128)
#pragma unroll 4
        for (int k = 0; k < BK; k++) {
            float4 v4 = *(const float4*)&Vs[k * VD + lane * 4];
#pragma unroll
            for (int i = 0; i < 4; i++) {
                float p = Ps[(w * 4 + i) * BK + k];
                acc[i][0] += p * v4.x;
                acc[i][1] += p * v4.y;
                acc[i][2] += p * v4.z;
                acc[i][3] += p * v4.w;
            }
        }
    }

#pragma unroll
    for (int i = 0; i < 4; i++) {
        const float inv = 1.0f / l_i[i];
        const int qg = qb * BQ + w * 4 + i;
        float4 o = make_float4(acc[i][0] * inv, acc[i][1] * inv,
                               acc[i][2] * inv, acc[i][3] * inv);
        *(float4*)&out[(size_t)qg * (NH * VD) + h * VD + lane * 4] = o;
    }
}

// ---------------- launch ----------------
extern "C" void kernel_launch(void* const* d_in, const int* in_sizes, int n_in,
                              void* d_out, int out_size)
{
    const float* hidden = (const float*)d_in[0];
    const float* w_q_a  = (const float*)d_in[1];
    const float* q_a_w  = (const float*)d_in[2];
    const float* w_q_b  = (const float*)d_in[3];
    const float* w_kv_a = (const float*)d_in[4];
    const float* kv_a_w = (const float*)d_in[5];
    const float* w_kv_b = (const float*)d_in[6];
    const float* w_o    = (const float*)d_in[7];
    float* out = (float*)d_out;

    float *qlat, *ckv, *ckvn, *qbuf, *kvbuf, *kpe, *attn;
    cudaGetSymbolAddress((void**)&qlat,  g_qlat);
    cudaGetSymbolAddress((void**)&ckv,   g_ckv);
    cudaGetSymbolAddress((void**)&ckvn,  g_ckvn);
    cudaGetSymbolAddress((void**)&qbuf,  g_q);
    cudaGetSymbolAddress((void**)&kvbuf, g_kv);
    cudaGetSymbolAddress((void**)&kpe,   g_kpe);
    cudaGetSymbolAddress((void**)&attn,  g_attn);

    const size_t attn_smem = (BQ * KPAD + BK * KPAD + BK * VD + BQ * BK) * sizeof(float);
    cudaFuncSetAttribute(attn_kernel, cudaFuncAttributeMaxDynamicSharedMemorySize,
                         (int)attn_smem);

    // 1. q latent = hidden @ w_q_a^T   [2048, 1536]
    gemm_nt<<<dim3(QLORA / GTN, S_LEN / GTM), 256>>>(hidden, w_q_a, qlat,
                                                     S_LEN, QLORA, HID);
    // 2. ckv = hidden @ w_kv_a^T       [2048, 576]
    gemm_nt<<<dim3((KVLORA + ROPED) / GTN, S_LEN / GTM), 256>>>(hidden, w_kv_a, ckv,
                                                                S_LEN, KVLORA + ROPED, HID);
    // 3. rmsnorm q latent (in place)
    rmsnorm_kernel<<<S_LEN, 256>>>(qlat, q_a_w, qlat, QLORA, QLORA, QLORA);
    // 4. rmsnorm compressed kv -> compact buffer
    rmsnorm_kernel<<<S_LEN, 256>>>(ckv, kv_a_w, ckvn, KVLORA, KVLORA + ROPED, KVLORA);
    // 5. q = qlat @ w_q_b^T            [2048, 3072]
    gemm_nt<<<dim3(NH * QHD / GTN, S_LEN / GTM), 256>>>(qlat, w_q_b, qbuf,
                                                        S_LEN, NH * QHD, QLORA);
    // 6. kv = ckvn @ w_kv_b^T          [2048, 4096]
    gemm_nt<<<dim3(NH * KVD / GTN, S_LEN / GTM), 256>>>(ckvn, w_kv_b, kvbuf,
                                                        S_LEN, NH * KVD, KVLORA);
    // 7. rope (q_pe in place; k_pe -> kpe)
    rope_kernel<<<S_LEN, 544>>>(qbuf, ckv, kpe);
    // 8. attention
    attn_kernel<<<dim3(S_LEN / BQ, NH), 256, attn_smem>>>(qbuf, kvbuf, kpe, attn);
    // 9. out = attn @ w_o^T            [2048, 2048]
    gemm_nt<<<dim3(HID / GTN, S_LEN / GTM), 256>>>(attn, w_o, out,
                                                   S_LEN, HID, HID);
}

// round 3
// speedup vs baseline: 1.4121x; 1.4121x over previous
#include <cuda_runtime.h>
#include <math.h>
#include <cstdint>

#define S_LEN  2048
#define HID    2048
#define NH     16
#define QLORA  1536
#define KVLORA 512
#define NOPE   128
#define ROPED  64
#define VD     128
#define QHD    192          // NOPE + ROPED
#define KVD    256          // NOPE + VD

// ---------------- scratch (no cudaMalloc allowed) ----------------
__device__ float g_qlat[S_LEN * QLORA];
__device__ float g_ckv [S_LEN * (KVLORA + ROPED)];
__device__ float g_ckvn[S_LEN * KVLORA];
__device__ float g_q   [S_LEN * NH * QHD];
__device__ float g_kv  [S_LEN * NH * KVD];
__device__ float g_kpe [S_LEN * ROPED];
__device__ float g_attn[S_LEN * NH * VD];

// ======================= helpers =======================
__device__ __forceinline__ uint32_t smem_u32(const void* p) {
    uint32_t a;
    asm("{ .reg .u64 t; cvta.to.shared.u64 t, %1; cvt.u32.u64 %0, t; }"
        : "=r"(a) : "l"(p));
    return a;
}
__device__ __forceinline__ uint32_t to_tf32(float x) {
    uint32_t u;
    asm("cvt.rna.tf32.f32 %0, %1;" : "=r"(u) : "f"(x));
    return u;
}
__device__ __forceinline__ void mma_tf32(float* d, const uint32_t* a,
                                         const uint32_t* b) {
    asm volatile(
        "mma.sync.aligned.m16n8k8.row.col.f32.tf32.tf32.f32 "
        "{%0,%1,%2,%3}, {%4,%5,%6,%7}, {%8,%9}, {%0,%1,%2,%3};"
        : "+f"(d[0]), "+f"(d[1]), "+f"(d[2]), "+f"(d[3])
        : "r"(a[0]), "r"(a[1]), "r"(a[2]), "r"(a[3]),
          "r"(b[0]), "r"(b[1]));
}

// ============ tf32 mma.sync GEMM: C[M,N] = A[M,K] @ B[N,K]^T ============
// CTA 128x128, K-tile 32, 256 threads (8 warps, 4x2), warp tile 32x64.
// SMEM per stage: A[128][36] + B[128][36] floats; 2 stages = 73728 B.
#define KT      32
#define LDS_W   36
#define STG_F   (128 * LDS_W)          // floats per (A or B) tile
#define GEMM_SMEM (2 * 2 * STG_F * 4)  // 73728 bytes

__global__ __launch_bounds__(256) void gemm_mma(
    const float* __restrict__ A, const float* __restrict__ B,
    float* __restrict__ C, int M, int N, int K)
{
    extern __shared__ float sm[];
    const int tid  = threadIdx.x;
    const int lane = tid & 31;
    const int w    = tid >> 5;
    const int g    = lane >> 2;      // group id 0..7
    const int t    = lane & 3;       // thread-in-group
    const int wm   = w & 3;          // warp m index (0..3)
    const int wn   = w >> 2;         // warp n index (0..1)
    const int bm   = blockIdx.y * 128;
    const int bn   = blockIdx.x * 128;

    const uint32_t sbase = smem_u32(sm);
    float acc[2][8][4] = {};
    const int NT = K / KT;

    // -------- async tile load --------
    auto issue = [&](int kt) {
        const int so = (kt & 1) * 2 * STG_F;     // float offset of stage
        const float* Ag = A + (size_t)bm * K + kt * KT;
        const float* Bg = B + (size_t)bn * K + kt * KT;
#pragma unroll
        for (int i = 0; i < 4; i++) {
            const int idx = tid + i * 256;       // 0..1023
            const int row = idx >> 3;
            const int c4  = (idx & 7) * 4;
            const uint32_t da = sbase + (so + row * LDS_W + c4) * 4;
            asm volatile("cp.async.ca.shared.global [%0], [%1], 16;"
                         :: "r"(da), "l"(Ag + (size_t)row * K + c4) : "memory");
            const uint32_t db = sbase + (so + STG_F + row * LDS_W + c4) * 4;
            const int sz = (bn + row < N) ? 16 : 0;
            asm volatile("cp.async.ca.shared.global [%0], [%1], 16, %2;"
                         :: "r"(db), "l"(Bg + (size_t)row * K + c4), "r"(sz)
                         : "memory");
        }
        asm volatile("cp.async.commit_group;" ::: "memory");
    };

    issue(0);

    for (int kt = 0; kt < NT; kt++) {
        if (kt + 1 < NT) {
            issue(kt + 1);
            asm volatile("cp.async.wait_group 1;" ::: "memory");
        } else {
            asm volatile("cp.async.wait_group 0;" ::: "memory");
        }
        __syncthreads();

        const float* As = sm + (kt & 1) * 2 * STG_F + (wm * 32) * LDS_W;
        const float* Bs = sm + (kt & 1) * 2 * STG_F + STG_F + (wn * 64) * LDS_W;
#pragma unroll
        for (int ks = 0; ks < 4; ks++) {
            const int k0 = ks * 8;
            uint32_t af[2][4];
#pragma unroll
            for (int mt = 0; mt < 2; mt++) {
                af[mt][0] = to_tf32(As[(mt * 16 + g)     * LDS_W + k0 + t]);
                af[mt][1] = to_tf32(As[(mt * 16 + 8 + g) * LDS_W + k0 + t]);
                af[mt][2] = to_tf32(As[(mt * 16 + g)     * LDS_W + k0 + t + 4]);
                af[mt][3] = to_tf32(As[(mt * 16 + 8 + g) * LDS_W + k0 + t + 4]);
            }
            uint32_t bf[8][2];
#pragma unroll
            for (int nt = 0; nt < 8; nt++) {
                bf[nt][0] = to_tf32(Bs[(nt * 8 + g) * LDS_W + k0 + t]);
                bf[nt][1] = to_tf32(Bs[(nt * 8 + g) * LDS_W + k0 + t + 4]);
            }
#pragma unroll
            for (int mt = 0; mt < 2; mt++)
#pragma unroll
                for (int nt = 0; nt < 8; nt++)
                    mma_tf32(acc[mt][nt], af[mt], bf[nt]);
        }
        __syncthreads();
    }

    // -------- epilogue --------
#pragma unroll
    for (int mt = 0; mt < 2; mt++) {
        const int row0 = bm + wm * 32 + mt * 16 + g;
#pragma unroll
        for (int nt = 0; nt < 8; nt++) {
            const int col = bn + wn * 64 + nt * 8 + 2 * t;
            if (col < N) {
                *(float2*)&C[(size_t)row0 * N + col] =
                    make_float2(acc[mt][nt][0], acc[mt][nt][1]);
                *(float2*)&C[(size_t)(row0 + 8) * N + col] =
                    make_float2(acc[mt][nt][2], acc[mt][nt][3]);
            }
        }
    }
}

// ---------------- RMSNorm over rows ----------------
__global__ __launch_bounds__(256) void rmsnorm_kernel(
    const float* __restrict__ x, const float* __restrict__ w,
    float* __restrict__ y, int ncols, int xstride, int ystride)
{
    const int row = blockIdx.x;
    const float* xr = x + (size_t)row * xstride;
    float* yr = y + (size_t)row * ystride;

    float ss = 0.f;
    for (int c = threadIdx.x; c < ncols; c += 256) {
        float v = xr[c];
        ss += v * v;
    }
    __shared__ float red[8];
#pragma unroll
    for (int o = 16; o; o >>= 1) ss += __shfl_xor_sync(~0u, ss, o);
    if ((threadIdx.x & 31) == 0) red[threadIdx.x >> 5] = ss;
    __syncthreads();
    if (threadIdx.x < 32) {
        float v = (threadIdx.x < 8) ? red[threadIdx.x] : 0.f;
#pragma unroll
        for (int o = 4; o; o >>= 1) v += __shfl_xor_sync(~0u, v, o);
        if (threadIdx.x == 0) red[0] = v;
    }
    __syncthreads();
    const float inv = rsqrtf(red[0] / (float)ncols + 1e-6f);
    for (int c = threadIdx.x; c < ncols; c += 256)
        yr[c] = xr[c] * inv * w[c];
}

// ---------------- RoPE ----------------
__global__ __launch_bounds__(544) void rope_kernel(
    float* __restrict__ q, const float* __restrict__ ckv, float* __restrict__ kpe)
{
    const int s = blockIdx.x;
    const int t = threadIdx.x;
    const int h = t >> 5;
    const int d = t & 31;

    const float f = powf(10000.0f, -(float)d / 32.0f);
    float sn, cs;
    sincosf((float)s * f, &sn, &cs);

    if (h < NH) {
        float* p = q + (size_t)s * (NH * QHD) + h * QHD + NOPE;
        float x1 = p[d], x2 = p[d + 32];
        p[d]      = x1 * cs - x2 * sn;
        p[d + 32] = x2 * cs + x1 * sn;
    } else {
        const float* p = ckv + (size_t)s * (KVLORA + ROPED) + KVLORA;
        float x1 = p[d], x2 = p[d + 32];
        kpe[s * ROPED + d]      = x1 * cs - x2 * sn;
        kpe[s * ROPED + d + 32] = x2 * cs + x1 * sn;
    }
}

// ---------------- Flash attention (causal), fp32 ----------------
#define BQ 32
#define BK 64
#define KPAD 196

__global__ __launch_bounds__(256) void attn_kernel(
    const float* __restrict__ q, const float* __restrict__ kv,
    const float* __restrict__ kpe, float* __restrict__ out)
{
    extern __shared__ float smf[];
    float* Qs = smf;
    float* Ks = Qs + BQ * KPAD;
    float* Vs = Ks + BK * KPAD;
    float* Ps = Vs + BK * VD;

    const int qb   = blockIdx.x;
    const int h    = blockIdx.y;
    const int tid  = threadIdx.x;
    const int w    = tid >> 5;
    const int lane = tid & 31;

    for (int idx = tid; idx < BQ * QHD; idx += 256) {
        int r = idx / QHD, d = idx % QHD;
        Qs[r * KPAD + d] = q[(size_t)(qb * BQ + r) * (NH * QHD) + h * QHD + d];
    }

    float acc[4][4] = {};
    float m_i[4] = {-1e30f, -1e30f, -1e30f, -1e30f};
    float l_i[4] = {};

    const int q_hi = qb * BQ + BQ - 1;
    const int nkb  = q_hi / BK + 1;
    const float scale = 0.07216878364870323f;

    for (int kb = 0; kb < nkb; kb++) {
        __syncthreads();
        for (int idx = tid; idx < BK * QHD; idx += 256) {
            int r = idx / QHD, d = idx % QHD;
            int kg = kb * BK + r;
            float v = (d < NOPE)
                ? kv[(size_t)kg * (NH * KVD) + h * KVD + d]
                : kpe[kg * ROPED + (d - NOPE)];
            Ks[r * KPAD + d] = v;
        }
        for (int idx = tid; idx < BK * VD; idx += 256) {
            int r = idx >> 7, d = idx & 127;
            Vs[r * VD + d] =
                kv[(size_t)(kb * BK + r) * (NH * KVD) + h * KVD + NOPE + d];
        }
        __syncthreads();

        float s0[4][2] = {};
#pragma unroll 2
        for (int d = 0; d < QHD; d += 4) {
            float4 k0 = *(const float4*)&Ks[(lane * 2 + 0) * KPAD + d];
            float4 k1 = *(const float4*)&Ks[(lane * 2 + 1) * KPAD + d];
#pragma unroll
            for (int i = 0; i < 4; i++) {
                float4 qv = *(const float4*)&Qs[(w * 4 + i) * KPAD + d];
                s0[i][0] += qv.x * k0.x + qv.y * k0.y + qv.z * k0.z + qv.w * k0.w;
                s0[i][1] += qv.x * k1.x + qv.y * k1.y + qv.z * k1.z + qv.w * k1.w;
            }
        }

#pragma unroll
        for (int i = 0; i < 4; i++) {
            const int qg = qb * BQ + w * 4 + i;
            const int kg0 = kb * BK + lane * 2;
            float v0 = (kg0     <= qg) ? s0[i][0] * scale : -1e30f;
            float v1 = (kg0 + 1 <= qg) ? s0[i][1] * scale : -1e30f;
            float mloc = fmaxf(v0, v1);
#pragma unroll
            for (int o = 16; o; o >>= 1)
                mloc = fmaxf(mloc, __shfl_xor_sync(~0u, mloc, o));
            const float mnew = fmaxf(m_i[i], mloc);
            const float corr = __expf(m_i[i] - mnew);
            m_i[i] = mnew;
            const float p0 = __expf(v0 - mnew);
            const float p1 = __expf(v1 - mnew);
            float rs = p0 + p1;
#pragma unroll
            for (int o = 16; o; o >>= 1) rs += __shfl_xor_sync(~0u, rs, o);
            l_i[i] = l_i[i] * corr + rs;
#pragma unroll
            for (int j = 0; j < 4; j++) acc[i][j] *= corr;
            *(float2*)&Ps[(w * 4 + i) * BK + lane * 2] = make_float2(p0, p1);
        }
        __syncwarp();

#pragma unroll 4
        for (int k = 0; k < BK; k++) {
            float4 v4 = *(const float4*)&Vs[k * VD + lane * 4];
#pragma unroll
            for (int i = 0; i < 4; i++) {
                float p = Ps[(w * 4 + i) * BK + k];
                acc[i][0] += p * v4.x;
                acc[i][1] += p * v4.y;
                acc[i][2] += p * v4.z;
                acc[i][3] += p * v4.w;
            }
        }
    }

#pragma unroll
    for (int i = 0; i < 4; i++) {
        const float inv = 1.0f / l_i[i];
        const int qg = qb * BQ + w * 4 + i;
        float4 o = make_float4(acc[i][0] * inv, acc[i][1] * inv,
                               acc[i][2] * inv, acc[i][3] * inv);
        *(float4*)&out[(size_t)qg * (NH * VD) + h * VD + lane * 4] = o;
    }
}

// ---------------- launch ----------------
extern "C" void kernel_launch(void* const* d_in, const int* in_sizes, int n_in,
                              void* d_out, int out_size)
{
    const float* hidden = (const float*)d_in[0];
    const float* w_q_a  = (const float*)d_in[1];
    const float* q_a_w  = (const float*)d_in[2];
    const float* w_q_b  = (const float*)d_in[3];
    const float* w_kv_a = (const float*)d_in[4];
    const float* kv_a_w = (const float*)d_in[5];
    const float* w_kv_b = (const float*)d_in[6];
    const float* w_o    = (const float*)d_in[7];
    float* out = (float*)d_out;

    float *qlat, *ckv, *ckvn, *qbuf, *kvbuf, *kpe, *attn;
    cudaGetSymbolAddress((void**)&qlat,  g_qlat);
    cudaGetSymbolAddress((void**)&ckv,   g_ckv);
    cudaGetSymbolAddress((void**)&ckvn,  g_ckvn);
    cudaGetSymbolAddress((void**)&qbuf,  g_q);
    cudaGetSymbolAddress((void**)&kvbuf, g_kv);
    cudaGetSymbolAddress((void**)&kpe,   g_kpe);
    cudaGetSymbolAddress((void**)&attn,  g_attn);

    const size_t attn_smem =
        (BQ * KPAD + BK * KPAD + BK * VD + BQ * BK) * sizeof(float);
    cudaFuncSetAttribute(gemm_mma, cudaFuncAttributeMaxDynamicSharedMemorySize,
                         GEMM_SMEM);
    cudaFuncSetAttribute(attn_kernel, cudaFuncAttributeMaxDynamicSharedMemorySize,
                         (int)attn_smem);

    // 1. q latent = hidden @ w_q_a^T   [2048, 1536]
    gemm_mma<<<dim3(QLORA / 128, S_LEN / 128), 256, GEMM_SMEM>>>(
        hidden, w_q_a, qlat, S_LEN, QLORA, HID);
    // 2. ckv = hidden @ w_kv_a^T       [2048, 576]
    gemm_mma<<<dim3((KVLORA + ROPED + 127) / 128, S_LEN / 128), 256, GEMM_SMEM>>>(
        hidden, w_kv_a, ckv, S_LEN, KVLORA + ROPED, HID);
    // 3. rmsnorm q latent (in place)
    rmsnorm_kernel<<<S_LEN, 256>>>(qlat, q_a_w, qlat, QLORA, QLORA, QLORA);
    // 4. rmsnorm compressed kv -> compact buffer
    rmsnorm_kernel<<<S_LEN, 256>>>(ckv, kv_a_w, ckvn, KVLORA, KVLORA + ROPED, KVLORA);
    // 5. q = qlat @ w_q_b^T            [2048, 3072]
    gemm_mma<<<dim3(NH * QHD / 128, S_LEN / 128), 256, GEMM_SMEM>>>(
        qlat, w_q_b, qbuf, S_LEN, NH * QHD, QLORA);
    // 6. kv = ckvn @ w_kv_b^T          [2048, 4096]
    gemm_mma<<<dim3(NH * KVD / 128, S_LEN / 128), 256, GEMM_SMEM>>>(
        ckvn, w_kv_b, kvbuf, S_LEN, NH * KVD, KVLORA);
    // 7. rope
    rope_kernel<<<S_LEN, 544>>>(qbuf, ckv, kpe);
    // 8. attention
    attn_kernel<<<dim3(S_LEN / BQ, NH), 256, attn_smem>>>(qbuf, kvbuf, kpe, attn);
    // 9. out = attn @ w_o^T            [2048, 2048]
    gemm_mma<<<dim3(HID / 128, S_LEN / 128), 256, GEMM_SMEM>>>(
        attn, w_o, out, S_LEN, HID, HID);
}

// round 4
// speedup vs baseline: 4.9694x; 3.5191x over previous
#include <cuda_runtime.h>
#include <math.h>
#include <cstdint>

#define S_LEN  2048
#define HID    2048
#define NH     16
#define QLORA  1536
#define KVLORA 512
#define NOPE   128
#define ROPED  64
#define VD     128
#define QHD    192          // NOPE + ROPED
#define KVD    256          // NOPE + VD

// ---------------- scratch (no cudaMalloc allowed) ----------------
__device__ float g_qlat[S_LEN * QLORA];
__device__ float g_ckv [S_LEN * (KVLORA + ROPED)];
__device__ float g_ckvn[S_LEN * KVLORA];
__device__ float g_q   [S_LEN * NH * QHD];
__device__ float g_kv  [S_LEN * NH * KVD];
__device__ float g_kpe [S_LEN * ROPED];
__device__ float g_attn[S_LEN * NH * VD];

// ======================= helpers =======================
__device__ __forceinline__ uint32_t smem_u32(const void* p) {
    uint32_t a;
    asm("{ .reg .u64 t; cvta.to.shared.u64 t, %1; cvt.u32.u64 %0, t; }"
        : "=r"(a) : "l"(p));
    return a;
}
__device__ __forceinline__ uint32_t to_tf32(float x) {
    uint32_t u;
    asm("cvt.rna.tf32.f32 %0, %1;" : "=r"(u) : "f"(x));
    return u;
}
__device__ __forceinline__ void mma_tf32(float* d, const uint32_t* a,
                                         const uint32_t* b) {
    asm volatile(
        "mma.sync.aligned.m16n8k8.row.col.f32.tf32.tf32.f32 "
        "{%0,%1,%2,%3}, {%4,%5,%6,%7}, {%8,%9}, {%0,%1,%2,%3};"
        : "+f"(d[0]), "+f"(d[1]), "+f"(d[2]), "+f"(d[3])
        : "r"(a[0]), "r"(a[1]), "r"(a[2]), "r"(a[3]),
          "r"(b[0]), "r"(b[1]));
}

// ============ tf32 mma.sync GEMM: C[M,N] = A[M,K] @ B[N,K]^T ============
#define KT      32
#define LDS_W   36
#define STG_F   (128 * LDS_W)
#define GEMM_SMEM (2 * 2 * STG_F * 4)

__global__ __launch_bounds__(256) void gemm_mma(
    const float* __restrict__ A, const float* __restrict__ B,
    float* __restrict__ C, int M, int N, int K)
{
    extern __shared__ float sm[];
    const int tid  = threadIdx.x;
    const int lane = tid & 31;
    const int w    = tid >> 5;
    const int g    = lane >> 2;
    const int t    = lane & 3;
    const int wm   = w & 3;
    const int wn   = w >> 2;
    const int bm   = blockIdx.y * 128;
    const int bn   = blockIdx.x * 128;

    const uint32_t sbase = smem_u32(sm);
    float acc[2][8][4] = {};
    const int NT = K / KT;

    auto issue = [&](int kt) {
        const int so = (kt & 1) * 2 * STG_F;
        const float* Ag = A + (size_t)bm * K + kt * KT;
        const float* Bg = B + (size_t)bn * K + kt * KT;
#pragma unroll
        for (int i = 0; i < 4; i++) {
            const int idx = tid + i * 256;
            const int row = idx >> 3;
            const int c4  = (idx & 7) * 4;
            const uint32_t da = sbase + (so + row * LDS_W + c4) * 4;
            asm volatile("cp.async.ca.shared.global [%0], [%1], 16;"
                         :: "r"(da), "l"(Ag + (size_t)row * K + c4) : "memory");
            const uint32_t db = sbase + (so + STG_F + row * LDS_W + c4) * 4;
            const int sz = (bn + row < N) ? 16 : 0;
            asm volatile("cp.async.ca.shared.global [%0], [%1], 16, %2;"
                         :: "r"(db), "l"(Bg + (size_t)row * K + c4), "r"(sz)
                         : "memory");
        }
        asm volatile("cp.async.commit_group;" ::: "memory");
    };

    issue(0);

    for (int kt = 0; kt < NT; kt++) {
        if (kt + 1 < NT) {
            issue(kt + 1);
            asm volatile("cp.async.wait_group 1;" ::: "memory");
        } else {
            asm volatile("cp.async.wait_group 0;" ::: "memory");
        }
        __syncthreads();

        const float* As = sm + (kt & 1) * 2 * STG_F + (wm * 32) * LDS_W;
        const float* Bs = sm + (kt & 1) * 2 * STG_F + STG_F + (wn * 64) * LDS_W;
#pragma unroll
        for (int ks = 0; ks < 4; ks++) {
            const int k0 = ks * 8;
            uint32_t af[2][4];
#pragma unroll
            for (int mt = 0; mt < 2; mt++) {
                af[mt][0] = to_tf32(As[(mt * 16 + g)     * LDS_W + k0 + t]);
                af[mt][1] = to_tf32(As[(mt * 16 + 8 + g) * LDS_W + k0 + t]);
                af[mt][2] = to_tf32(As[(mt * 16 + g)     * LDS_W + k0 + t + 4]);
                af[mt][3] = to_tf32(As[(mt * 16 + 8 + g) * LDS_W + k0 + t + 4]);
            }
            uint32_t bf[8][2];
#pragma unroll
            for (int nt = 0; nt < 8; nt++) {
                bf[nt][0] = to_tf32(Bs[(nt * 8 + g) * LDS_W + k0 + t]);
                bf[nt][1] = to_tf32(Bs[(nt * 8 + g) * LDS_W + k0 + t + 4]);
            }
#pragma unroll
            for (int mt = 0; mt < 2; mt++)
#pragma unroll
                for (int nt = 0; nt < 8; nt++)
                    mma_tf32(acc[mt][nt], af[mt], bf[nt]);
        }
        __syncthreads();
    }

#pragma unroll
    for (int mt = 0; mt < 2; mt++) {
        const int row0 = bm + wm * 32 + mt * 16 + g;
#pragma unroll
        for (int nt = 0; nt < 8; nt++) {
            const int col = bn + wn * 64 + nt * 8 + 2 * t;
            if (col < N) {
                *(float2*)&C[(size_t)row0 * N + col] =
                    make_float2(acc[mt][nt][0], acc[mt][nt][1]);
                *(float2*)&C[(size_t)(row0 + 8) * N + col] =
                    make_float2(acc[mt][nt][2], acc[mt][nt][3]);
            }
        }
    }
}

// ---------------- RMSNorm ----------------
__global__ __launch_bounds__(256) void rmsnorm_kernel(
    const float* __restrict__ x, const float* __restrict__ w,
    float* __restrict__ y, int ncols, int xstride, int ystride)
{
    const int row = blockIdx.x;
    const float* xr = x + (size_t)row * xstride;
    float* yr = y + (size_t)row * ystride;

    float ss = 0.f;
    for (int c = threadIdx.x; c < ncols; c += 256) {
        float v = xr[c];
        ss += v * v;
    }
    __shared__ float red[8];
#pragma unroll
    for (int o = 16; o; o >>= 1) ss += __shfl_xor_sync(~0u, ss, o);
    if ((threadIdx.x & 31) == 0) red[threadIdx.x >> 5] = ss;
    __syncthreads();
    if (threadIdx.x < 32) {
        float v = (threadIdx.x < 8) ? red[threadIdx.x] : 0.f;
#pragma unroll
        for (int o = 4; o; o >>= 1) v += __shfl_xor_sync(~0u, v, o);
        if (threadIdx.x == 0) red[0] = v;
    }
    __syncthreads();
    const float inv = rsqrtf(red[0] / (float)ncols + 1e-6f);
    for (int c = threadIdx.x; c < ncols; c += 256)
        yr[c] = xr[c] * inv * w[c];
}

// ---------------- RoPE ----------------
__global__ __launch_bounds__(544) void rope_kernel(
    float* __restrict__ q, const float* __restrict__ ckv, float* __restrict__ kpe)
{
    const int s = blockIdx.x;
    const int t = threadIdx.x;
    const int h = t >> 5;
    const int d = t & 31;

    const float f = powf(10000.0f, -(float)d / 32.0f);
    float sn, cs;
    sincosf((float)s * f, &sn, &cs);

    if (h < NH) {
        float* p = q + (size_t)s * (NH * QHD) + h * QHD + NOPE;
        float x1 = p[d], x2 = p[d + 32];
        p[d]      = x1 * cs - x2 * sn;
        p[d + 32] = x2 * cs + x1 * sn;
    } else {
        const float* p = ckv + (size_t)s * (KVLORA + ROPED) + KVLORA;
        float x1 = p[d], x2 = p[d + 32];
        kpe[s * ROPED + d]      = x1 * cs - x2 * sn;
        kpe[s * ROPED + d + 32] = x2 * cs + x1 * sn;
    }
}

// ======== Tensorized flash attention (causal, tf32 mma.sync) ========
// BQ=64, BK=64, 256 threads = 8 warps: wm=wid&3 (16-row stripe), wn=wid>>2.
#define KP 196
#define VP 132
#define PP 68
#define OFF_KS0 0
#define OFF_KS1 12544
#define OFF_VS0 25088
#define OFF_VS1 33536
#define OFF_PS  41984
#define OFF_MB  46336
#define OFF_SB  46464
#define ATTN_SMEM (46592 * 4)

__global__ __launch_bounds__(256) void attn_mma(
    const float* __restrict__ q, const float* __restrict__ kv,
    const float* __restrict__ kpe, float* __restrict__ out)
{
    extern __shared__ float smf[];
    const int tid = threadIdx.x, lane = tid & 31, wid = tid >> 5;
    const int wm = wid & 3, wn = wid >> 2;
    const int g = lane >> 2, t = lane & 3;
    const int qb = (int)gridDim.x - 1 - (int)blockIdx.x;   // big tiles first
    const int h  = blockIdx.y;
    const uint32_t sbase = smem_u32(smf);

    // Q fragments in registers, pre-scaled, tf32
    uint32_t qf[24][4];
    {
        const float sc = 0.07216878364870323f;  // 192^-0.5
        const float* Qg = q + (size_t)(qb * 64 + wm * 16) * (NH * QHD) + h * QHD;
#pragma unroll
        for (int kc = 0; kc < 24; kc++) {
            qf[kc][0] = to_tf32(sc * Qg[(size_t)g       * (NH * QHD) + kc * 8 + t]);
            qf[kc][1] = to_tf32(sc * Qg[(size_t)(g + 8) * (NH * QHD) + kc * 8 + t]);
            qf[kc][2] = to_tf32(sc * Qg[(size_t)g       * (NH * QHD) + kc * 8 + t + 4]);
            qf[kc][3] = to_tf32(sc * Qg[(size_t)(g + 8) * (NH * QHD) + kc * 8 + t + 4]);
        }
    }

    float oa[8][4] = {};
    float m0 = -1e30f, m1 = -1e30f, l0 = 0.f, l1 = 0.f;

    auto fill = [&](int kb) {
        const int buf = kb & 1;
        const uint32_t kd = sbase + (buf ? OFF_KS1 : OFF_KS0) * 4;
        const uint32_t vd = sbase + (buf ? OFF_VS1 : OFF_VS0) * 4;
        const float* kvb = kv + (size_t)(kb * 64) * (NH * KVD) + h * KVD;
#pragma unroll
        for (int i = 0; i < 12; i++) {
            int idx = tid + i * 256;               // 0..3071
            int r = idx / 48, c4 = (idx % 48) * 4; // 48 float4 per K row
            const float* src = (c4 < 128)
                ? (kvb + (size_t)r * (NH * KVD) + c4)
                : (kpe + (size_t)(kb * 64 + r) * ROPED + (c4 - 128));
            uint32_t d = kd + (r * KP + c4) * 4;
            asm volatile("cp.async.ca.shared.global [%0], [%1], 16;"
                         :: "r"(d), "l"(src) : "memory");
        }
#pragma unroll
        for (int i = 0; i < 8; i++) {
            int idx = tid + i * 256;               // 0..2047
            int r = idx >> 5, c4 = (idx & 31) * 4;
            const float* src = kvb + (size_t)r * (NH * KVD) + NOPE + c4;
            uint32_t d = vd + (r * VP + c4) * 4;
            asm volatile("cp.async.ca.shared.global [%0], [%1], 16;"
                         :: "r"(d), "l"(src) : "memory");
        }
        asm volatile("cp.async.commit_group;" ::: "memory");
    };

    fill(0);

    float* Ps   = smf + OFF_PS;
    float* maxb = smf + OFF_MB;
    float* sumb = smf + OFF_SB;
    const int lr0 = wm * 16 + g;

    for (int kb = 0; kb <= qb; kb++) {
        __syncthreads();                // prev readers done -> buffers free
        if (kb < qb) {
            fill(kb + 1);
            asm volatile("cp.async.wait_group 1;" ::: "memory");
        } else {
            asm volatile("cp.async.wait_group 0;" ::: "memory");
        }
        __syncthreads();

        const float* Ks = smf + ((kb & 1) ? OFF_KS1 : OFF_KS0);
        const float* Vs = smf + ((kb & 1) ? OFF_VS1 : OFF_VS0);

        // ---- S = (Q*scale) @ K^T ----
        float sf[4][4] = {};
#pragma unroll
        for (int kc = 0; kc < 24; kc++) {
            uint32_t bf[4][2];
#pragma unroll
            for (int nt = 0; nt < 4; nt++) {
                const float* kr = Ks + (wn * 32 + nt * 8 + g) * KP + kc * 8;
                bf[nt][0] = to_tf32(kr[t]);
                bf[nt][1] = to_tf32(kr[t + 4]);
            }
#pragma unroll
            for (int nt = 0; nt < 4; nt++)
                mma_tf32(sf[nt], qf[kc], bf[nt]);
        }

        // ---- causal mask + row max ----
        const int r0g = qb * 64 + lr0;
        const int r1g = r0g + 8;
        float pm0 = -1e30f, pm1 = -1e30f;
        const bool diag = (kb == qb);
#pragma unroll
        for (int nt = 0; nt < 4; nt++) {
            const int c = kb * 64 + wn * 32 + nt * 8 + 2 * t;
            if (diag) {
                if (c     > r0g) sf[nt][0] = -1e30f;
                if (c + 1 > r0g) sf[nt][1] = -1e30f;
                if (c     > r1g) sf[nt][2] = -1e30f;
                if (c + 1 > r1g) sf[nt][3] = -1e30f;
            }
            pm0 = fmaxf(pm0, fmaxf(sf[nt][0], sf[nt][1]));
            pm1 = fmaxf(pm1, fmaxf(sf[nt][2], sf[nt][3]));
        }
        pm0 = fmaxf(pm0, __shfl_xor_sync(~0u, pm0, 1));
        pm0 = fmaxf(pm0, __shfl_xor_sync(~0u, pm0, 2));
        pm1 = fmaxf(pm1, __shfl_xor_sync(~0u, pm1, 1));
        pm1 = fmaxf(pm1, __shfl_xor_sync(~0u, pm1, 2));
        if (t == 0) { maxb[wn * 64 + lr0] = pm0; maxb[wn * 64 + lr0 + 8] = pm1; }
        __syncthreads();
        pm0 = fmaxf(pm0, maxb[(1 - wn) * 64 + lr0]);
        pm1 = fmaxf(pm1, maxb[(1 - wn) * 64 + lr0 + 8]);
        const float mn0 = fmaxf(m0, pm0), mn1 = fmaxf(m1, pm1);
        const float cr0 = __expf(m0 - mn0), cr1 = __expf(m1 - mn1);
        m0 = mn0; m1 = mn1;

        // ---- exp, write P (tf32), partial sums ----
        float ps0 = 0.f, ps1 = 0.f;
#pragma unroll
        for (int nt = 0; nt < 4; nt++) {
            float p0 = __expf(sf[nt][0] - mn0);
            float p1 = __expf(sf[nt][1] - mn0);
            float p2 = __expf(sf[nt][2] - mn1);
            float p3 = __expf(sf[nt][3] - mn1);
            ps0 += p0 + p1; ps1 += p2 + p3;
            float* pr = Ps + lr0 * PP + wn * 32 + nt * 8 + 2 * t;
            *(float2*)pr = make_float2(__uint_as_float(to_tf32(p0)),
                                       __uint_as_float(to_tf32(p1)));
            *(float2*)(pr + 8 * PP) = make_float2(__uint_as_float(to_tf32(p2)),
                                                  __uint_as_float(to_tf32(p3)));
        }
        ps0 += __shfl_xor_sync(~0u, ps0, 1);
        ps0 += __shfl_xor_sync(~0u, ps0, 2);
        ps1 += __shfl_xor_sync(~0u, ps1, 1);
        ps1 += __shfl_xor_sync(~0u, ps1, 2);
        if (t == 0) { sumb[wn * 64 + lr0] = ps0; sumb[wn * 64 + lr0 + 8] = ps1; }
        __syncthreads();
        l0 = l0 * cr0 + sumb[lr0] + sumb[64 + lr0];
        l1 = l1 * cr1 + sumb[lr0 + 8] + sumb[64 + lr0 + 8];
#pragma unroll
        for (int nt = 0; nt < 8; nt++) {
            oa[nt][0] *= cr0; oa[nt][1] *= cr0;
            oa[nt][2] *= cr1; oa[nt][3] *= cr1;
        }

        // ---- O += P @ V ----
#pragma unroll
        for (int kc = 0; kc < 8; kc++) {
            uint32_t pf[4];
            const float* p0p = Ps + lr0 * PP + kc * 8;
            pf[0] = __float_as_uint(p0p[t]);
            pf[1] = __float_as_uint(p0p[8 * PP + t]);
            pf[2] = __float_as_uint(p0p[t + 4]);
            pf[3] = __float_as_uint(p0p[8 * PP + t + 4]);
#pragma unroll
            for (int nt = 0; nt < 8; nt++) {
                uint32_t bv[2];
                const float* vr = Vs + (kc * 8 + t) * VP + wn * 64 + nt * 8 + g;
                bv[0] = to_tf32(vr[0]);
                bv[1] = to_tf32(vr[4 * VP]);
                mma_tf32(oa[nt], pf, bv);
            }
        }
    }

    // ---- normalize + write ----
    const float i0 = 1.f / l0, i1 = 1.f / l1;
    const int r0g = qb * 64 + lr0;
#pragma unroll
    for (int nt = 0; nt < 8; nt++) {
        const int c = wn * 64 + nt * 8 + 2 * t;
        float* o0 = out + (size_t)r0g * (NH * VD) + h * VD + c;
        *(float2*)o0 = make_float2(oa[nt][0] * i0, oa[nt][1] * i0);
        *(float2*)(o0 + (size_t)8 * (NH * VD)) =
            make_float2(oa[nt][2] * i1, oa[nt][3] * i1);
    }
}

// ---------------- launch ----------------
extern "C" void kernel_launch(void* const* d_in, const int* in_sizes, int n_in,
                              void* d_out, int out_size)
{
    const float* hidden = (const float*)d_in[0];
    const float* w_q_a  = (const float*)d_in[1];
    const float* q_a_w  = (const float*)d_in[2];
    const float* w_q_b  = (const float*)d_in[3];
    const float* w_kv_a = (const float*)d_in[4];
    const float* kv_a_w = (const float*)d_in[5];
    const float* w_kv_b = (const float*)d_in[6];
    const float* w_o    = (const float*)d_in[7];
    float* out = (float*)d_out;

    float *qlat, *ckv, *ckvn, *qbuf, *kvbuf, *kpe, *attn;
    cudaGetSymbolAddress((void**)&qlat,  g_qlat);
    cudaGetSymbolAddress((void**)&ckv,   g_ckv);
    cudaGetSymbolAddress((void**)&ckvn,  g_ckvn);
    cudaGetSymbolAddress((void**)&qbuf,  g_q);
    cudaGetSymbolAddress((void**)&kvbuf, g_kv);
    cudaGetSymbolAddress((void**)&kpe,   g_kpe);
    cudaGetSymbolAddress((void**)&attn,  g_attn);

    cudaFuncSetAttribute(gemm_mma, cudaFuncAttributeMaxDynamicSharedMemorySize,
                         GEMM_SMEM);
    cudaFuncSetAttribute(attn_mma, cudaFuncAttributeMaxDynamicSharedMemorySize,
                         ATTN_SMEM);

    // 1. q latent = hidden @ w_q_a^T   [2048, 1536]
    gemm_mma<<<dim3(QLORA / 128, S_LEN / 128), 256, GEMM_SMEM>>>(
        hidden, w_q_a, qlat, S_LEN, QLORA, HID);
    // 2. ckv = hidden @ w_kv_a^T       [2048, 576]
    gemm_mma<<<dim3((KVLORA + ROPED + 127) / 128, S_LEN / 128), 256, GEMM_SMEM>>>(
        hidden, w_kv_a, ckv, S_LEN, KVLORA + ROPED, HID);
    // 3. rmsnorm q latent (in place)
    rmsnorm_kernel<<<S_LEN, 256>>>(qlat, q_a_w, qlat, QLORA, QLORA, QLORA);
    // 4. rmsnorm compressed kv
    rmsnorm_kernel<<<S_LEN, 256>>>(ckv, kv_a_w, ckvn, KVLORA, KVLORA + ROPED, KVLORA);
    // 5. q = qlat @ w_q_b^T            [2048, 3072]
    gemm_mma<<<dim3(NH * QHD / 128, S_LEN / 128), 256, GEMM_SMEM>>>(
        qlat, w_q_b, qbuf, S_LEN, NH * QHD, QLORA);
    // 6. kv = ckvn @ w_kv_b^T          [2048, 4096]
    gemm_mma<<<dim3(NH * KVD / 128, S_LEN / 128), 256, GEMM_SMEM>>>(
        ckvn, w_kv_b, kvbuf, S_LEN, NH * KVD, KVLORA);
    // 7. rope
    rope_kernel<<<S_LEN, 544>>>(qbuf, ckv, kpe);
    // 8. attention (tensorized)
    attn_mma<<<dim3(S_LEN / 64, NH), 256, ATTN_SMEM>>>(qbuf, kvbuf, kpe, attn);
    // 9. out = attn @ w_o^T            [2048, 2048]
    gemm_mma<<<dim3(HID / 128, S_LEN / 128), 256, GEMM_SMEM>>>(
        attn, w_o, out, S_LEN, HID, HID);
}